// round 17
// baseline (speedup 1.0000x reference)
#include <cuda_runtime.h>
#include <math.h>

// SimpleLSTM: B=4096, T_HIST=60, D_IN=2, H=128, L=2, T_OUT=360
// Persistent kernel, MROWS=4 rows/block, grid=1024, 7 CTAs/SM (balanced
// single wave on 148 SMs). Rank-2 embedding fold; float4-packed k-major
// weights (2x LDG.128/k2); broadcast LDS.128 x loads; double-buffered h;
// packed fma.rn.f32x2; MUFU fast sigmoid/tanh.

#define MROWS   4
#define NPAIR   2          // MROWS/2
#define HDIM    128
#define NTHREAD 128
#define T_HIST  60
#define T_OUT   360
#define XSTRIDE 2          // row stride in float2: 16B rows (one ulonglong2)

typedef unsigned long long ull;

// Packed transposed weights: mats 0:eWih0 1:eWih1 2:eWhh0 3:eWhh1 4:dWih0
// 5:dWih1 6:dWhh0 7:dWhh1. Layout [mat][k2*256 + gp*128 + tid] float4 =
// (W[r0][2k2], W[r0][2k2+1], W[r1][2k2], W[r1][2k2+1]), r0=gp*256+tid, r1=r0+128.
__device__ float4 g_W4[8][64 * 256];
// Rank-2 folded layer-0 input terms: [enc/dec][u0,u1,ub+bias][512 gate rows]
__device__ float  g_U[2][3][512];
// Combined layer-1 biases [enc/dec][512]; decoder layer-0 plain bias [512]
__device__ float  g_B1[2][512];
__device__ float  g_BD0[512];

__device__ __forceinline__ ull ffma2(ull a, ull b, ull c) {
    ull d;
    asm("fma.rn.f32x2 %0, %1, %2, %3;" : "=l"(d) : "l"(a), "l"(b), "l"(c));
    return d;
}
__device__ __forceinline__ ull dup2(float w) {
    ull d;
    asm("mov.b64 %0, {%1, %1};" : "=l"(d) : "f"(w));
    return d;
}
__device__ __forceinline__ ull pack2(float a, float b) {
    ull d;
    asm("mov.b64 %0, {%1, %2};" : "=l"(d) : "f"(a), "f"(b));
    return d;
}
__device__ __forceinline__ void unpack2(ull v, float& a, float& b) {
    asm("mov.b64 {%0, %1}, %2;" : "=f"(a), "=f"(b) : "l"(v));
}
__device__ __forceinline__ float sigf(float x) {
    float e = __expf(-x);
    return __fdividef(1.0f, 1.0f + e);
}
__device__ __forceinline__ float tanh_fast(float x) {
    float e = __expf(-2.0f * x);
    return __fdividef(1.0f - e, 1.0f + e);
}

// ---------------- prep kernel 1: weight transpose + float4 pack ----------------
__global__ void transpose_weights(
    const float* __restrict__ eWih, const float* __restrict__ eWhh,
    const float* __restrict__ dWih, const float* __restrict__ dWhh)
{
    int idx = blockIdx.x * 256 + threadIdx.x;   // 0 .. 8*16384-1
    int mat = idx >> 14;
    int rem = idx & 16383;
    int k2  = rem >> 8;
    int q   = rem & 255;
    int gp  = q >> 7;
    int tid = q & 127;
    int grp = mat >> 1;
    int lay = mat & 1;
    const float* src =
        (grp == 0 ? eWih : grp == 1 ? eWhh : grp == 2 ? dWih : dWhh) + lay * 65536;
    int r0 = gp * 256 + tid;
    int r1 = r0 + 128;
    g_W4[mat][k2 * 256 + gp * 128 + tid] = make_float4(
        src[r0 * 128 + 2 * k2], src[r0 * 128 + 2 * k2 + 1],
        src[r1 * 128 + 2 * k2], src[r1 * 128 + 2 * k2 + 1]);
}

// ---------------- prep kernel 2: rank-2 folding + bias combine ----------------
__global__ void prep_rank2(
    const float* __restrict__ eWih, const float* __restrict__ dWih,
    const float* __restrict__ emb_W, const float* __restrict__ emb_b,
    const float* __restrict__ enc_bih, const float* __restrict__ enc_bhh,
    const float* __restrict__ dec_bih, const float* __restrict__ dec_bhh)
{
    int idx = blockIdx.x * 256 + threadIdx.x;   // 0..1023
    int mat = idx >> 9;                          // 0 enc, 1 dec
    int row = idx & 511;
    const float* W = (mat ? dWih : eWih) + row * 128;   // layer 0
    float a0 = 0.0f, a1 = 0.0f, ab = 0.0f;
    for (int k = 0; k < 128; ++k) {
        float w = W[k];
        a0 += w * emb_W[2 * k];
        a1 += w * emb_W[2 * k + 1];
        ab += w * emb_b[k];
    }
    const float* bi = mat ? dec_bih : enc_bih;
    const float* bh = mat ? dec_bhh : enc_bhh;
    g_U[mat][0][row] = a0;
    g_U[mat][1][row] = a1;
    g_U[mat][2][row] = ab + bi[row] + bh[row];
    g_B1[mat][row] = bi[512 + row] + bh[512 + row];
    if (mat == 1) g_BD0[row] = bi[row] + bh[row];
}

// ---------------- gate GEMM on batch-row pairs ----------------
__device__ __forceinline__ void gemm_pairs(
    ull (&acc)[NPAIR][4],
    const float2* __restrict__ xb,      // shared, k-major [128][XSTRIDE]
    const float4* __restrict__ W4,      // global, [64][2][128]
    int tid)
{
#pragma unroll 4
    for (int k2 = 0; k2 < 64; ++k2) {
        float4 wa = __ldg(&W4[k2 * 256 + tid]);         // gates i,f
        float4 wb = __ldg(&W4[k2 * 256 + 128 + tid]);   // gates g,o

        // x rows are 16B: one broadcast LDS.128 per k (all lanes same row)
        ulonglong2 x0 = *(const ulonglong2*)(xb + (2 * k2)     * XSTRIDE);
        ulonglong2 x1 = *(const ulonglong2*)(xb + (2 * k2 + 1) * XSTRIDE);
        ull xa[NPAIR] = { x0.x, x0.y };
        ull xc[NPAIR] = { x1.x, x1.y };

        // k-even contributions
        {
            ull a0 = dup2(wa.x), a1 = dup2(wa.z);
            ull a2 = dup2(wb.x), a3 = dup2(wb.z);
#pragma unroll
            for (int p = 0; p < NPAIR; ++p) {
                acc[p][0] = ffma2(a0, xa[p], acc[p][0]);
                acc[p][1] = ffma2(a1, xa[p], acc[p][1]);
                acc[p][2] = ffma2(a2, xa[p], acc[p][2]);
                acc[p][3] = ffma2(a3, xa[p], acc[p][3]);
            }
        }
        // k-odd contributions
        {
            ull b0 = dup2(wa.y), b1 = dup2(wa.w);
            ull b2 = dup2(wb.y), b3 = dup2(wb.w);
#pragma unroll
            for (int p = 0; p < NPAIR; ++p) {
                acc[p][0] = ffma2(b0, xc[p], acc[p][0]);
                acc[p][1] = ffma2(b1, xc[p], acc[p][1]);
                acc[p][2] = ffma2(b2, xc[p], acc[p][2]);
                acc[p][3] = ffma2(b3, xc[p], acc[p][3]);
            }
        }
    }
}

// Gate nonlinearity + state update into the NEXT buffer (double-buffered).
__device__ __forceinline__ void gate_update(
    ull (&acc)[NPAIR][4],
    float2* __restrict__ hnew,
    float (&cst)[MROWS],
    int tid)
{
#pragma unroll
    for (int p = 0; p < NPAIR; ++p) {
        float i0, i1, f0, f1, g0, g1, o0, o1;
        unpack2(acc[p][0], i0, i1);
        unpack2(acc[p][1], f0, f1);
        unpack2(acc[p][2], g0, g1);
        unpack2(acc[p][3], o0, o1);
        float c0 = sigf(f0) * cst[2 * p]     + sigf(i0) * tanh_fast(g0);
        float c1 = sigf(f1) * cst[2 * p + 1] + sigf(i1) * tanh_fast(g1);
        cst[2 * p]     = c0;
        cst[2 * p + 1] = c1;
        float h0 = sigf(o0) * tanh_fast(c0);
        float h1 = sigf(o1) * tanh_fast(c1);
        *(ull*)(hnew + tid * XSTRIDE + p) = pack2(h0, h1);
    }
    __syncthreads();
}

__global__ __launch_bounds__(NTHREAD, 7)
void lstm_persistent_kernel(
    const float* __restrict__ history,   // (B, 60, 2)
    const float* __restrict__ out_W,     // (2, 128)
    const float* __restrict__ out_b,     // (2)
    float* __restrict__ out)             // (B, 360, 2)
{
    __shared__ __align__(16) float2 hp0[2][HDIM * XSTRIDE];
    __shared__ __align__(16) float2 hp1[2][HDIM * XSTRIDE];
    __shared__ float  hist_sh[T_HIST * MROWS * 2];   // [t][row][d]
    __shared__ float  pred_sh[MROWS][2];
    __shared__ float  outw_sh[2][HDIM];
    __shared__ float  outb_sh[2];

    const int tid = threadIdx.x;
    const int b0  = blockIdx.x * MROWS;

    outw_sh[0][tid] = out_W[tid];
    outw_sh[1][tid] = out_W[128 + tid];
    if (tid < 2) outb_sh[tid] = out_b[tid];

    // Preload this block's history window (coalesced)
    for (int g = tid; g < T_HIST * MROWS * 2; g += NTHREAD) {
        int row = g / (T_HIST * 2);
        int r   = g - row * (T_HIST * 2);    // t*2 + d
        hist_sh[(r >> 1) * (MROWS * 2) + row * 2 + (r & 1)] =
            history[(size_t)(b0 + row) * (T_HIST * 2) + r];
    }

    float cst0[MROWS], cst1[MROWS];
#pragma unroll
    for (int m = 0; m < MROWS; ++m) { cst0[m] = 0.0f; cst1[m] = 0.0f; }
#pragma unroll
    for (int p = 0; p < NPAIR; ++p) {
        hp0[0][tid * XSTRIDE + p] = make_float2(0.0f, 0.0f);
        hp1[0][tid * XSTRIDE + p] = make_float2(0.0f, 0.0f);
    }
    __syncthreads();

    const float4* eU0 = g_W4[2];   // enc layer0 Whh
    const float4* eW1 = g_W4[1];   // enc layer1 Wih
    const float4* eU1 = g_W4[3];   // enc layer1 Whh
    const float4* dU0 = g_W4[6];   // dec layer0 Whh
    const float4* dW1 = g_W4[5];   // dec layer1 Wih
    const float4* dU1 = g_W4[7];   // dec layer1 Whh

    ull acc[NPAIR][4];
    int cur = 0;

    // ---------------- Encoder: 60 steps ----------------
    for (int t = 0; t < T_HIST; ++t) {
        int nxt = cur ^ 1;
        // Layer 0: rank-2 input term + Whh GEMM
        {
            const float* hs = hist_sh + t * (MROWS * 2);
            ull pp0[NPAIR], pp1[NPAIR];
#pragma unroll
            for (int p = 0; p < NPAIR; ++p) {
                pp0[p] = pack2(hs[4 * p],     hs[4 * p + 2]);
                pp1[p] = pack2(hs[4 * p + 1], hs[4 * p + 3]);
            }
#pragma unroll
            for (int j = 0; j < 4; ++j) {
                int g = tid + 128 * j;
                ull a0 = dup2(g_U[0][0][g]);
                ull a1 = dup2(g_U[0][1][g]);
                ull ab = dup2(g_U[0][2][g]);
#pragma unroll
                for (int p = 0; p < NPAIR; ++p)
                    acc[p][j] = ffma2(a0, pp0[p], ffma2(a1, pp1[p], ab));
            }
        }
        gemm_pairs(acc, hp0[cur], eU0, tid);
        gate_update(acc, hp0[nxt], cst0, tid);

        // Layer 1
#pragma unroll
        for (int j = 0; j < 4; ++j) {
            ull b = dup2(g_B1[0][tid + 128 * j]);
#pragma unroll
            for (int p = 0; p < NPAIR; ++p) acc[p][j] = b;
        }
        gemm_pairs(acc, hp0[nxt], eW1, tid);
        gemm_pairs(acc, hp1[cur], eU1, tid);
        gate_update(acc, hp1[nxt], cst1, tid);

        cur = nxt;
    }

    // ---------------- Decoder: 360 autoregressive steps ----------------
    const int wrp  = tid >> 5;
    const int lane = tid & 31;

    for (int t = 0; t < T_OUT; ++t) {
        int nxt = cur ^ 1;
        // Layer 0: rank-2 input term (pred feedback) + Whh GEMM
        if (t == 0) {
#pragma unroll
            for (int j = 0; j < 4; ++j) {
                ull b = dup2(g_BD0[tid + 128 * j]);
#pragma unroll
                for (int p = 0; p < NPAIR; ++p) acc[p][j] = b;
            }
        } else {
            ull pp0[NPAIR], pp1[NPAIR];
#pragma unroll
            for (int p = 0; p < NPAIR; ++p) {
                pp0[p] = pack2(pred_sh[2 * p][0], pred_sh[2 * p + 1][0]);
                pp1[p] = pack2(pred_sh[2 * p][1], pred_sh[2 * p + 1][1]);
            }
#pragma unroll
            for (int j = 0; j < 4; ++j) {
                int g = tid + 128 * j;
                ull a0 = dup2(g_U[1][0][g]);
                ull a1 = dup2(g_U[1][1][g]);
                ull ab = dup2(g_U[1][2][g]);
#pragma unroll
                for (int p = 0; p < NPAIR; ++p)
                    acc[p][j] = ffma2(a0, pp0[p], ffma2(a1, pp1[p], ab));
            }
        }
        gemm_pairs(acc, hp0[cur], dU0, tid);
        gate_update(acc, hp0[nxt], cst0, tid);

        // Layer 1
#pragma unroll
        for (int j = 0; j < 4; ++j) {
            ull b = dup2(g_B1[1][tid + 128 * j]);
#pragma unroll
            for (int p = 0; p < NPAIR; ++p) acc[p][j] = b;
        }
        gemm_pairs(acc, hp0[nxt], dW1, tid);
        gemm_pairs(acc, hp1[cur], dU1, tid);
        gate_update(acc, hp1[nxt], cst1, tid);

        // pred = h1 @ out_W.T + out_b ; warps 0,1 handle pairs 0,1
        if (wrp < NPAIR) {
            int p = wrp;
            float a00 = 0.0f, a01 = 0.0f, a10 = 0.0f, a11 = 0.0f;
#pragma unroll
            for (int j = 0; j < 4; ++j) {
                int k = lane + 32 * j;
                float2 hv = hp1[nxt][k * XSTRIDE + p];
                float w0 = outw_sh[0][k];
                float w1 = outw_sh[1][k];
                a00 += hv.x * w0;  a01 += hv.x * w1;
                a10 += hv.y * w0;  a11 += hv.y * w1;
            }
#pragma unroll
            for (int off = 16; off > 0; off >>= 1) {
                a00 += __shfl_xor_sync(0xffffffffu, a00, off);
                a01 += __shfl_xor_sync(0xffffffffu, a01, off);
                a10 += __shfl_xor_sync(0xffffffffu, a10, off);
                a11 += __shfl_xor_sync(0xffffffffu, a11, off);
            }
            if (lane == 0) {
                float p00 = a00 + outb_sh[0];
                float p01 = a01 + outb_sh[1];
                float p10 = a10 + outb_sh[0];
                float p11 = a11 + outb_sh[1];
                int m0 = 2 * p, m1 = 2 * p + 1;
                pred_sh[m0][0] = p00;  pred_sh[m0][1] = p01;
                pred_sh[m1][0] = p10;  pred_sh[m1][1] = p11;
                size_t o0 = (size_t)(b0 + m0) * (T_OUT * 2) + (size_t)t * 2;
                size_t o1 = (size_t)(b0 + m1) * (T_OUT * 2) + (size_t)t * 2;
                out[o0] = p00;  out[o0 + 1] = p01;
                out[o1] = p10;  out[o1 + 1] = p11;
            }
        }
        __syncthreads();   // pred_sh stable for next step

        cur = nxt;
    }
}

extern "C" void kernel_launch(void* const* d_in, const int* in_sizes, int n_in,
                              void* d_out, int out_size)
{
    const float* history = (const float*)d_in[0];
    const float* emb_W   = (const float*)d_in[1];
    const float* emb_b   = (const float*)d_in[2];
    const float* enc_Wih = (const float*)d_in[3];
    const float* enc_Whh = (const float*)d_in[4];
    const float* enc_bih = (const float*)d_in[5];
    const float* enc_bhh = (const float*)d_in[6];
    const float* dec_Wih = (const float*)d_in[7];
    const float* dec_Whh = (const float*)d_in[8];
    const float* dec_bih = (const float*)d_in[9];
    const float* dec_bhh = (const float*)d_in[10];
    const float* out_W   = (const float*)d_in[11];
    const float* out_b   = (const float*)d_in[12];
    float* out = (float*)d_out;

    transpose_weights<<<512, 256>>>(enc_Wih, enc_Whh, dec_Wih, dec_Whh);
    prep_rank2<<<4, 256>>>(enc_Wih, dec_Wih, emb_W, emb_b,
                           enc_bih, enc_bhh, dec_bih, dec_bhh);

    const int B = 4096;
    lstm_persistent_kernel<<<B / MROWS, NTHREAD>>>(
        history, out_W, out_b, out);
}